// round 9
// baseline (speedup 1.0000x reference)
#include <cuda_runtime.h>
#include <cuda_fp16.h>
#include <cstdint>

#define BATCH   8192
#define DIM     64
#define HID     128
#define NSTEPS  100
#define THREADS 128
#define NBLK    128

// ---- smem layout (bytes) ----
#define P1 144u   // W1^T row pitch: 64 fp16 = 128B + 16B pad
#define P2 272u   // W2^T row pitch: 128 fp16 = 256B + 16B pad
#define W1D_OFF 0u
#define W1G_OFF 18432u       // 128*144
#define W2D_OFF 36864u
#define W2G_OFF 54272u       // + 64*272
#define B1D_OFF 71680u
#define B1G_OFF 72192u
#define B2D_OFF 72704u
#define B2G_OFF 72960u
#define XB_OFF  73216u       // x fp32 [2 pairs][2 tiles][8 t][32 lanes][16B] = 16KB
#define PC2_OFF 89600u       // peer C2 [2 pairs][2 dirs][8 t][32 lanes][16B] = 16KB
#define XH_OFF  105984u      // x frags [2 pairs][2 tiles][4 kk][32 lanes][16B] = 8KB
#define SMEM_TOTAL 114176u

__device__ __forceinline__ uint32_t smem_u32(const void* p) {
    uint32_t a;
    asm("{ .reg .u64 t; cvta.to.shared.u64 t, %1; cvt.u32.u64 %0, t; }"
        : "=r"(a) : "l"(p));
    return a;
}

__device__ __forceinline__ float tanh_fast(float v) {
    float r;
    asm("tanh.approx.f32 %0, %1;" : "=f"(r) : "f"(v));
    return r;
}

__device__ __forceinline__ void mma_f16(float* c, const uint32_t* a,
                                        uint32_t b0, uint32_t b1) {
    asm volatile(
        "mma.sync.aligned.m16n8k16.row.col.f32.f16.f16.f32 "
        "{%0,%1,%2,%3}, {%4,%5,%6,%7}, {%8,%9}, {%0,%1,%2,%3};"
        : "+f"(c[0]), "+f"(c[1]), "+f"(c[2]), "+f"(c[3])
        : "r"(a[0]), "r"(a[1]), "r"(a[2]), "r"(a[3]), "r"(b0), "r"(b1));
}

__device__ __forceinline__ void ldsm4(uint32_t* r, uint32_t addr) {
    asm volatile("ldmatrix.sync.aligned.m8n8.x4.shared.b16 {%0,%1,%2,%3}, [%4];"
                 : "=r"(r[0]), "=r"(r[1]), "=r"(r[2]), "=r"(r[3]) : "r"(addr));
}

__device__ __forceinline__ uint32_t packh(float lo, float hi) {
    __half2 h = __floats2half2_rn(lo, hi);
    return *reinterpret_cast<uint32_t*>(&h);
}

__global__ void __launch_bounds__(THREADS, 1)
sde_m32_kernel(const float* __restrict__ x0,
               const float* __restrict__ noise,
               const float* __restrict__ Wd1, const float* __restrict__ bd1,
               const float* __restrict__ Wd2, const float* __restrict__ bd2,
               const float* __restrict__ Wg1, const float* __restrict__ bg1,
               const float* __restrict__ Wg2, const float* __restrict__ bg2,
               float* __restrict__ out)
{
    extern __shared__ char smc[];
    const uint32_t smem_base = smem_u32(smc);
    const int tid = threadIdx.x;

    // ---- stage weights (fp16, transposed [n][k], padded pitch) ----
    for (int idx = tid; idx < DIM * HID; idx += THREADS) {     // W1: [64 k][128 n]
        int k = idx >> 7, n = idx & 127;
        *(__half*)(smc + W1D_OFF + (uint32_t)n * P1 + 2*k) = __float2half_rn(Wd1[idx]);
        *(__half*)(smc + W1G_OFF + (uint32_t)n * P1 + 2*k) = __float2half_rn(Wg1[idx]);
    }
    for (int idx = tid; idx < HID * DIM; idx += THREADS) {     // W2: [128 k][64 n]
        int k = idx >> 6, n = idx & 63;
        *(__half*)(smc + W2D_OFF + (uint32_t)n * P2 + 2*k) = __float2half_rn(Wd2[idx]);
        *(__half*)(smc + W2G_OFF + (uint32_t)n * P2 + 2*k) = __float2half_rn(Wg2[idx]);
    }
    for (int i = tid; i < HID; i += THREADS) {
        ((float*)(smc + B1D_OFF))[i] = bd1[i];
        ((float*)(smc + B1G_OFF))[i] = bg1[i];
    }
    for (int i = tid; i < DIM; i += THREADS) {
        ((float*)(smc + B2D_OFF))[i] = bd2[i];
        ((float*)(smc + B2G_OFF))[i] = bg2[i];
    }

    const int wid  = tid >> 5, lane = tid & 31;
    const int pair = wid & 1;             // pair p: warps {p (f), p+2 (g)}
    const bool isF = (wid < 2);
    const int tileOwn = isF ? 0 : 1;      // f updates tile0, g updates tile1
    const int g = lane >> 2;
    const int cpair = (lane & 3) * 2;
    const int rowBase = blockIdx.x * 64 + pair * 32;   // 2 tiles: +0..15, +16..31
    const int rowOwn  = rowBase + tileOwn * 16 + g;    // own tile rows: rowOwn, rowOwn+8
    const int barid = 1 + pair;

    // ldmatrix per-lane base address components
    const int rowA = (lane & 7) + ((lane >> 4) << 3);
    const uint32_t colo = (uint32_t)((lane >> 3) & 1) * 16u;
    const uint32_t g1 = smem_base + (isF ? W1D_OFF : W1G_OFF) + (uint32_t)rowA * P1 + colo;
    const uint32_t g2 = smem_base + (isF ? W2D_OFF : W2G_OFF) + (uint32_t)rowA * P2 + colo;

    const float* sb1  = (const float*)(smc + (isF ? B1D_OFF : B1G_OFF));
    const float* sb2d = (const float*)(smc + B2D_OFF);
    const float* sb2g = (const float*)(smc + B2G_OFF);

    // buffers
    char* xbOwn  = smc + XB_OFF  + (uint32_t)pair * 8192u + (uint32_t)tileOwn * 4096u
                 + (uint32_t)lane * 16u;
    // PC2: dir 0 = g's C2[tile0] (read by f); dir 1 = f's C2[tile1] (read by g)
    char* pc2Wr  = smc + PC2_OFF + (uint32_t)pair * 8192u + (uint32_t)(isF ? 1 : 0) * 4096u
                 + (uint32_t)lane * 16u;
    char* pc2Rd  = smc + PC2_OFF + (uint32_t)pair * 8192u + (uint32_t)(isF ? 0 : 1) * 4096u
                 + (uint32_t)lane * 16u;
    char* xhOwn  = smc + XH_OFF  + (uint32_t)pair * 4096u + (uint32_t)tileOwn * 2048u
                 + (uint32_t)lane * 16u;
    char* xhPeer = smc + XH_OFF  + (uint32_t)pair * 4096u + (uint32_t)(tileOwn ^ 1) * 2048u
                 + (uint32_t)lane * 16u;

    __syncthreads();

    // ---- init: each warp loads x0 of its OWN tile, seeds smem x + xh + out[0] ----
    uint32_t xh[2][4][4];
    {
        #pragma unroll
        for (int t = 0; t < 8; t++) {
            float2 v0 = *(const float2*)(x0 + (size_t)rowOwn * DIM + 8*t + cpair);
            float2 v1 = *(const float2*)(x0 + (size_t)(rowOwn + 8) * DIM + 8*t + cpair);
            *(float2*)(out + (size_t)rowOwn * DIM + 8*t + cpair) = v0;
            *(float2*)(out + (size_t)(rowOwn + 8) * DIM + 8*t + cpair) = v1;
            *(float4*)(xbOwn + t * 512) = make_float4(v0.x, v0.y, v1.x, v1.y);
            int kk = t >> 1, s = (t & 1) * 2;
            xh[tileOwn][kk][s]     = packh(v0.x, v0.y);
            xh[tileOwn][kk][s + 1] = packh(v1.x, v1.y);
        }
        #pragma unroll
        for (int kk = 0; kk < 4; kk++)
            *(uint4*)(xhOwn + kk * 512) =
                make_uint4(xh[tileOwn][kk][0], xh[tileOwn][kk][1],
                           xh[tileOwn][kk][2], xh[tileOwn][kk][3]);
    }
    __syncthreads();
    {
        int tp = tileOwn ^ 1;
        #pragma unroll
        for (int kk = 0; kk < 4; kk++) {
            uint4 v = *(uint4*)(xhPeer + kk * 512);
            xh[tp][kk][0] = v.x; xh[tp][kk][1] = v.y;
            xh[tp][kk][2] = v.z; xh[tp][kk][3] = v.w;
        }
    }

    const float DTC = 0.01f;
    const float SDT = 0.1f;

    #pragma unroll 1
    for (int step = 0; step < NSTEPS; ++step) {
        // noise prefetch for OWN tile (consumed at update, ~whole step of latency slack)
        float nz[8][4];
        {
            const float* nb = noise + (size_t)step * BATCH * DIM;
            #pragma unroll
            for (int t = 0; t < 8; t++) {
                float2 v0 = *(const float2*)(nb + (size_t)rowOwn * DIM + 8*t + cpair);
                float2 v1 = *(const float2*)(nb + (size_t)(rowOwn + 8) * DIM + 8*t + cpair);
                nz[t][0] = v0.x * SDT; nz[t][1] = v0.y * SDT;
                nz[t][2] = v1.x * SDT; nz[t][3] = v1.y * SDT;
            }
        }

        // ---- GEMM1 (M=32, both tiles) fused with tanh per n16 tile ----
        uint32_t Hp[2][8][4];
        #pragma unroll
        for (int t2 = 0; t2 < 8; t2++) {
            float cAlo[4] = {0,0,0,0}, cAhi[4] = {0,0,0,0};
            float cBlo[4] = {0,0,0,0}, cBhi[4] = {0,0,0,0};
            #pragma unroll
            for (int kk = 0; kk < 4; kk++) {
                uint32_t b[4];
                ldsm4(b, g1 + (uint32_t)t2 * (16u * P1) + (uint32_t)kk * 32u);
                mma_f16(cAlo, xh[0][kk], b[0], b[1]);
                mma_f16(cAhi, xh[0][kk], b[2], b[3]);
                mma_f16(cBlo, xh[1][kk], b[0], b[1]);
                mma_f16(cBhi, xh[1][kk], b[2], b[3]);
            }
            float2 blo = *(const float2*)(sb1 + 16*t2 + cpair);
            float2 bhi = *(const float2*)(sb1 + 16*t2 + 8 + cpair);
            Hp[0][t2][0] = packh(tanh_fast(cAlo[0] + blo.x), tanh_fast(cAlo[1] + blo.y));
            Hp[0][t2][1] = packh(tanh_fast(cAlo[2] + blo.x), tanh_fast(cAlo[3] + blo.y));
            Hp[0][t2][2] = packh(tanh_fast(cAhi[0] + bhi.x), tanh_fast(cAhi[1] + bhi.y));
            Hp[0][t2][3] = packh(tanh_fast(cAhi[2] + bhi.x), tanh_fast(cAhi[3] + bhi.y));
            Hp[1][t2][0] = packh(tanh_fast(cBlo[0] + blo.x), tanh_fast(cBlo[1] + blo.y));
            Hp[1][t2][1] = packh(tanh_fast(cBlo[2] + blo.x), tanh_fast(cBlo[3] + blo.y));
            Hp[1][t2][2] = packh(tanh_fast(cBhi[0] + bhi.x), tanh_fast(cBhi[1] + bhi.y));
            Hp[1][t2][3] = packh(tanh_fast(cBhi[2] + bhi.x), tanh_fast(cBhi[3] + bhi.y));
        }

        // ---- GEMM2 (M=32, both tiles) ----
        float C2[2][8][4];
        #pragma unroll
        for (int tl = 0; tl < 2; tl++)
            #pragma unroll
            for (int t = 0; t < 8; t++)
                { C2[tl][t][0]=0.f; C2[tl][t][1]=0.f; C2[tl][t][2]=0.f; C2[tl][t][3]=0.f; }
        #pragma unroll
        for (int kk = 0; kk < 8; kk++) {
            #pragma unroll
            for (int g2i = 0; g2i < 4; g2i++) {
                uint32_t b[4];
                ldsm4(b, g2 + (uint32_t)g2i * (16u * P2) + (uint32_t)kk * 32u);
                mma_f16(C2[0][2*g2i],   Hp[0][kk], b[0], b[1]);
                mma_f16(C2[0][2*g2i+1], Hp[0][kk], b[2], b[3]);
                mma_f16(C2[1][2*g2i],   Hp[1][kk], b[0], b[1]);
                mma_f16(C2[1][2*g2i+1], Hp[1][kk], b[2], b[3]);
            }
        }

        // ---- publish the NON-owned tile's C2 to the peer warp ----
        {
            int tp = tileOwn ^ 1;
            #pragma unroll
            for (int t = 0; t < 8; t++)
                *(float4*)(pc2Wr + t * 512) =
                    make_float4(C2[tp][t][0], C2[tp][t][1], C2[tp][t][2], C2[tp][t][3]);
        }
        asm volatile("bar.sync %0, %1;" :: "r"(barid), "n"(64) : "memory");

        // ---- update OWN tile: x' = x + f*dt + g*(dw*sdt) ----
        float* ob = out + (size_t)(step + 1) * BATCH * DIM;
        #pragma unroll
        for (int t = 0; t < 8; t++) {
            float4 pc = *(const float4*)(pc2Rd + t * 512);   // peer MLP raw values
            float4 xo = *(const float4*)(xbOwn + t * 512);
            float2 b2d = *(const float2*)(sb2d + 8*t + cpair);
            float2 b2g = *(const float2*)(sb2g + 8*t + cpair);
            float f0, f1, f2, f3, gg0, gg1, gg2, gg3;
            if (isF) {
                f0 = C2[0][t][0] + b2d.x; f1 = C2[0][t][1] + b2d.y;
                f2 = C2[0][t][2] + b2d.x; f3 = C2[0][t][3] + b2d.y;
                gg0 = pc.x + b2g.x; gg1 = pc.y + b2g.y;
                gg2 = pc.z + b2g.x; gg3 = pc.w + b2g.y;
            } else {
                f0 = pc.x + b2d.x; f1 = pc.y + b2d.y;
                f2 = pc.z + b2d.x; f3 = pc.w + b2d.y;
                gg0 = C2[1][t][0] + b2g.x; gg1 = C2[1][t][1] + b2g.y;
                gg2 = C2[1][t][2] + b2g.x; gg3 = C2[1][t][3] + b2g.y;
            }
            float n0 = fmaf(gg0, nz[t][0], fmaf(f0, DTC, xo.x));
            float n1 = fmaf(gg1, nz[t][1], fmaf(f1, DTC, xo.y));
            float n2 = fmaf(gg2, nz[t][2], fmaf(f2, DTC, xo.z));
            float n3 = fmaf(gg3, nz[t][3], fmaf(f3, DTC, xo.w));
            *(float4*)(xbOwn + t * 512) = make_float4(n0, n1, n2, n3);
            *(float2*)(ob + (size_t)rowOwn * DIM + 8*t + cpair)       = make_float2(n0, n1);
            *(float2*)(ob + (size_t)(rowOwn + 8) * DIM + 8*t + cpair) = make_float2(n2, n3);
            int kk = t >> 1, s = (t & 1) * 2;
            xh[tileOwn][kk][s]     = packh(n0, n1);
            xh[tileOwn][kk][s + 1] = packh(n2, n3);
        }
        #pragma unroll
        for (int kk = 0; kk < 4; kk++)
            *(uint4*)(xhOwn + kk * 512) =
                make_uint4(xh[tileOwn][kk][0], xh[tileOwn][kk][1],
                           xh[tileOwn][kk][2], xh[tileOwn][kk][3]);
        asm volatile("bar.sync %0, %1;" :: "r"(barid), "n"(64) : "memory");
        {
            int tp = tileOwn ^ 1;
            #pragma unroll
            for (int kk = 0; kk < 4; kk++) {
                uint4 v = *(uint4*)(xhPeer + kk * 512);
                xh[tp][kk][0] = v.x; xh[tp][kk][1] = v.y;
                xh[tp][kk][2] = v.z; xh[tp][kk][3] = v.w;
            }
        }
    }
}

extern "C" void kernel_launch(void* const* d_in, const int* in_sizes, int n_in,
                              void* d_out, int out_size)
{
    const float* x0    = (const float*)d_in[0];
    const float* noise = (const float*)d_in[2];
    const float* Wd1   = (const float*)d_in[3];
    const float* bd1   = (const float*)d_in[4];
    const float* Wd2   = (const float*)d_in[5];
    const float* bd2   = (const float*)d_in[6];
    const float* Wg1   = (const float*)d_in[7];
    const float* bg1   = (const float*)d_in[8];
    const float* Wg2   = (const float*)d_in[9];
    const float* bg2   = (const float*)d_in[10];
    float* out = (float*)d_out;

    cudaFuncSetAttribute(sde_m32_kernel,
                         cudaFuncAttributeMaxDynamicSharedMemorySize, SMEM_TOTAL);
    sde_m32_kernel<<<NBLK, THREADS, SMEM_TOTAL>>>(
        x0, noise, Wd1, bd1, Wd2, bd2, Wg1, bg1, Wg2, bg2, out);
}